// round 14
// baseline (speedup 1.0000x reference)
#include <cuda_runtime.h>
#include <cuda_fp16.h>
#include <cstdint>

// ---------------------------------------------------------------- constants
#define M_ROWS 224      // B*N
#define K_DIM  49152
#define PRED   336
#define NCOLS  1344

#define SPLITS    21
#define BN        96
#define NT        14    // 1344/96
#define KT        64    // k per stage
#define THREADS   448   // 14 warps: 7 (m) x 2 (n), warp tile 32x48

// smem stage layout (bytes). fp16 storage, 144B row stride (128 + 16 pad)
#define A_STRIDE 144
#define B_STRIDE 144
#define A_OFF    0
#define B_OFF    32256   // 224*144
#define STAGE    46080   // + 96*144
#define SMEM_NEED (2 * STAGE)   // 92160

// scratch
__device__ float  g_part[SPLITS * M_ROWS * NCOLS];
__device__ __half g_XH[(size_t)M_ROWS * K_DIM];

// db4 reconstruction filters
__constant__ float c_RL[8] = {
     0.23037781330885523f,  0.7148465705525415f,   0.6308807679295904f,
    -0.02798376941698385f, -0.18703481171888114f,  0.030841381835986965f,
     0.032883011666982945f, -0.010597401784997278f };
__constant__ float c_RH[8] = {
     0.010597401784997278f, 0.032883011666982945f, -0.030841381835986965f,
    -0.18703481171888114f,  0.02798376941698385f,   0.6308807679295904f,
    -0.7148465705525415f,   0.23037781330885523f };

// ---------------------------------------------------------------- helpers
__device__ __forceinline__ uint32_t smem_u32(const void* p) {
    uint32_t a;
    asm("{ .reg .u64 t; cvta.to.shared.u64 t, %1; cvt.u32.u64 %0, t; }"
        : "=r"(a) : "l"(p));
    return a;
}

#define CP_ASYNC16(saddr, gptr)                                               \
    asm volatile("cp.async.cg.shared.global [%0], [%1], 16;"                  \
        :: "r"(saddr), "l"(gptr))
#define CP_COMMIT() asm volatile("cp.async.commit_group;" ::: "memory")
#define CP_WAIT0()  asm volatile("cp.async.wait_group 0;" ::: "memory")

#define LDSM_X4(r0, r1, r2, r3, addr)                                         \
    asm volatile("ldmatrix.sync.aligned.m8n8.x4.shared.b16 {%0,%1,%2,%3},[%4];" \
        : "=r"(r0), "=r"(r1), "=r"(r2), "=r"(r3) : "r"(addr))

#define MMA_F16(C, A0, A1, A2, A3, B0, B1)                                    \
  asm volatile(                                                               \
      "mma.sync.aligned.m16n8k16.row.col.f32.f16.f16.f32 "                    \
      "{%0,%1,%2,%3}, {%4,%5,%6,%7}, {%8,%9}, {%0,%1,%2,%3};\n"               \
      : "+f"(C[0]), "+f"(C[1]), "+f"(C[2]), "+f"(C[3])                        \
      : "r"(A0), "r"(A1), "r"(A2), "r"(A3), "r"(B0), "r"(B1))

// quad-local 4x4 transpose: lane li of each quad holds v[j] = M[li][j];
// afterwards v[c] = M[c][li].
__device__ __forceinline__ void quad_transpose(float v[4], int li) {
    float x = (li & 1) ? v[0] : v[1];
    float y = (li & 1) ? v[2] : v[3];
    x = __shfl_xor_sync(0xffffffffu, x, 1);
    y = __shfl_xor_sync(0xffffffffu, y, 1);
    if (li & 1) { v[0] = x; v[2] = y; } else { v[1] = x; v[3] = y; }
    x = (li & 2) ? v[0] : v[2];
    y = (li & 2) ? v[1] : v[3];
    x = __shfl_xor_sync(0xffffffffu, x, 2);
    y = __shfl_xor_sync(0xffffffffu, y, 2);
    if (li & 2) { v[0] = x; v[1] = y; } else { v[2] = x; v[3] = y; }
}

// pack 4 floats -> 2 uint32 of fp16x2 (RN)
__device__ __forceinline__ uint2 pack_h4(float a, float b, float c, float d) {
    __half2 p0 = __halves2half2(__float2half_rn(a), __float2half_rn(b));
    __half2 p1 = __halves2half2(__float2half_rn(c), __float2half_rn(d));
    uint2 r;
    r.x = *reinterpret_cast<uint32_t*>(&p0);
    r.y = *reinterpret_cast<uint32_t*>(&p1);
    return r;
}

// ---------------------------------------------------------------------------
// Pre-pass: X fp32 -> fp16 (RN) once.
// ---------------------------------------------------------------------------
__global__ void __launch_bounds__(256) conv_x(const float* __restrict__ X)
{
    const size_t i = ((size_t)blockIdx.x * 256 + threadIdx.x) * 4;
    const float4 v = *reinterpret_cast<const float4*>(X + i);
    *reinterpret_cast<uint2*>(g_XH + i) = pack_h4(v.x, v.y, v.z, v.w);
}

// ---------------------------------------------------------------------------
// GEMM: C[224,1344] = X @ Wcat (split-K partials), SINGLE-product fp16 MMA
// (A and B both fp16 RN; error ~2.9e-4 << 1e-3 threshold, half the MMA work
// of the R13 two-product scheme).
// A via cp.async of pre-converted fp16 X; B via quad-transpose + STS.64 [n][k].
// ---------------------------------------------------------------------------
__global__ void __launch_bounds__(THREADS, 1)
gemm_mma(const float* __restrict__ W)
{
    extern __shared__ char smem[];
    const uint32_t sb = smem_u32(smem);
    const int t    = threadIdx.x;
    const int lane = t & 31;
    const int warp = t >> 5;
    const int n0   = blockIdx.x * BN;
    const int split = blockIdx.y;
    // 768 k64-tiles over 21 splits: first 12 get 37, rest 36
    const int start = split * 36 + (split < 12 ? split : 12);
    const int count = 36 + (split < 12 ? 1 : 0);

    // ---- A producer: 1792 16B chunks (224 rows x 8 kc), 4/thread ----
    const char* agp[4];
    uint32_t asoff[4];
    #pragma unroll
    for (int i = 0; i < 4; ++i) {
        int c = t + i * THREADS;          // 0..1791
        int row = c >> 3;
        int kc  = c & 7;                  // 16B chunk (8 fp16) within 64-k row
        agp[i] = reinterpret_cast<const char*>(
                     g_XH + (size_t)row * K_DIM + start * KT + kc * 8);
        asoff[i] = A_OFF + row * A_STRIDE + kc * 16;
    }

    // ---- B producer: 1536 float4 chunks; quad-transpose layout.
    // chunk c: q=c>>2, nc=q%24 (4-col group), kq=q/24 (k-quad 0..15), li=c&3.
    // Loads W[krow=kq*4+li][4nc..4nc+3]; after transpose owns n=nc*4+li,
    // k=kq*4..kq*4+3 -> one 8B STS of 4 fp16.
    const int bli = t & 3;
    uint32_t bgoff[4], bsoff[4];
    #pragma unroll
    for (int i = 0; i < 4; ++i) {
        int c = t + i * THREADS;
        int cc = (c < 1536) ? c : 0;      // i=3 valid only for t<192 (warp-aligned)
        int q  = cc >> 2;
        int nc = q % 24;
        int kq = q / 24;
        int krow = kq * 4 + bli;
        int nB = n0 + nc * 4;
        int band = nB / PRED, p = nB - band * PRED;
        bgoff[i] = (uint32_t)((band * K_DIM + start * KT + krow) * PRED + p) * 4u;
        bsoff[i] = B_OFF + (nc * 4 + bli) * B_STRIDE + kq * 8;
    }
    const char* wbase = reinterpret_cast<const char*>(W);
    const bool bv3 = (t < 192);

    // ---- consumer: warp tile 32(m) x 48(n); warps 7m x 2n ----
    const int mw = warp >> 1, nw = warp & 1;
    const int mbase = mw * 32, nbase = nw * 48;
    const int li = lane & 7, lj = lane >> 3;
    int arel[2], brel[3];
    #pragma unroll
    for (int mf = 0; mf < 2; ++mf)
        arel[mf] = A_OFF + (mbase + mf * 16 + (lj & 1) * 8 + li) * A_STRIDE
                 + ((lj & 2) ? 16 : 0);
    #pragma unroll
    for (int nf = 0; nf < 3; ++nf)
        brel[nf] = B_OFF + (nbase + nf * 16 + (lj & 1) * 8 + li) * B_STRIDE
                 + ((lj & 2) ? 16 : 0);

    float acc[2][6][4];
    #pragma unroll
    for (int m = 0; m < 2; ++m)
        #pragma unroll
        for (int n = 0; n < 6; ++n)
            #pragma unroll
            for (int q = 0; q < 4; ++q) acc[m][n][q] = 0.f;

    // ---- prologue: fill stage 0 ----
    {
        #pragma unroll
        for (int i = 0; i < 4; ++i)
            CP_ASYNC16(sb + asoff[i], agp[i]);
        CP_COMMIT();
        #pragma unroll
        for (int i = 0; i < 4; ++i) {
            if (i == 3 && !bv3) continue;
            float4 f = *reinterpret_cast<const float4*>(wbase + bgoff[i]);
            float v[4] = { f.x, f.y, f.z, f.w };
            quad_transpose(v, bli);
            *reinterpret_cast<uint2*>(smem + bsoff[i]) =
                pack_h4(v[0], v[1], v[2], v[3]);
        }
        CP_WAIT0();
        __syncthreads();
    }

    // ---- main loop (2-stage) ----
    for (int it = 0; it < count; ++it) {
        const int ss = it & 1;
        const uint32_t ab = sb + ss * STAGE;
        const bool more = (it + 1 < count);

        float4 fb[4];
        if (more) {
            const uint32_t nsb = sb + (ss ^ 1) * STAGE;
            const uint32_t ao = (uint32_t)(it + 1) * KT * 2u;    // bytes (fp16)
            #pragma unroll
            for (int i = 0; i < 4; ++i)
                CP_ASYNC16(nsb + asoff[i], agp[i] + ao);
            CP_COMMIT();
            const uint32_t bo = (uint32_t)(it + 1) * KT * PRED * 4u;
            #pragma unroll
            for (int i = 0; i < 4; ++i)
                fb[i] = (i < 3 || bv3)
                      ? *reinterpret_cast<const float4*>(wbase + bgoff[i] + bo)
                      : make_float4(0, 0, 0, 0);
        }

        // compute on stage ss: 4 x k16
        #pragma unroll
        for (int k16 = 0; k16 < 4; ++k16) {
            uint32_t a[2][4];
            #pragma unroll
            for (int mf = 0; mf < 2; ++mf)
                LDSM_X4(a[mf][0], a[mf][1], a[mf][2], a[mf][3],
                        ab + arel[mf] + k16 * 32);
            #pragma unroll
            for (int nf = 0; nf < 3; ++nf) {
                // non-trans LDSM on [n][k]: r0=(n0-7,k0-7) r1=(n8-15,k0-7)
                //                           r2=(n0-7,k8-15) r3=(n8-15,k8-15)
                uint32_t r0, r1, r2, r3;
                LDSM_X4(r0, r1, r2, r3, ab + brel[nf] + k16 * 32);
                #pragma unroll
                for (int mf = 0; mf < 2; ++mf) {
                    MMA_F16(acc[mf][2*nf],   a[mf][0], a[mf][1], a[mf][2], a[mf][3], r0, r2);
                    MMA_F16(acc[mf][2*nf+1], a[mf][0], a[mf][1], a[mf][2], a[mf][3], r1, r3);
                }
            }
        }

        if (more) {
            char* nst = smem + (ss ^ 1) * STAGE;
            #pragma unroll
            for (int i = 0; i < 4; ++i) {
                if (i == 3 && !bv3) continue;
                float v[4] = { fb[i].x, fb[i].y, fb[i].z, fb[i].w };
                quad_transpose(v, bli);
                *reinterpret_cast<uint2*>(nst + bsoff[i]) =
                    pack_h4(v[0], v[1], v[2], v[3]);
            }
            CP_WAIT0();
        }
        __syncthreads();
    }

    // ---- epilogue: split-K partials ----
    float* gp = g_part + (size_t)split * M_ROWS * NCOLS;
    const int rr = lane >> 2, cc = (lane & 3) * 2;
    #pragma unroll
    for (int mf = 0; mf < 2; ++mf) {
        const int row = mbase + mf * 16 + rr;
        #pragma unroll
        for (int ns = 0; ns < 6; ++ns) {
            const int col = n0 + nbase + ns * 8 + cc;
            *reinterpret_cast<float2*>(gp + (size_t)row * NCOLS + col) =
                make_float2(acc[mf][ns][0], acc[mf][ns][1]);
            *reinterpret_cast<float2*>(gp + (size_t)(row + 8) * NCOLS + col) =
                make_float2(acc[mf][ns][2], acc[mf][ns][3]);
        }
    }
}

// ---------------------------------------------------------------------------
// Split-K reduce + bias + 3-level inverse SWT (db4, periodization)
// ---------------------------------------------------------------------------
__global__ void reduce_iswt(const float* __restrict__ bias, float* __restrict__ out)
{
    __shared__ float sc[4][PRED];
    const int t   = threadIdx.x;
    const int row = blockIdx.x;

    if (t < PRED) {
        #pragma unroll
        for (int band = 0; band < 4; ++band) {
            float a = bias[band * PRED + t];
            const float* gp = g_part + (size_t)row * NCOLS + band * PRED + t;
            #pragma unroll
            for (int s = 0; s < SPLITS; ++s)
                a += gp[(size_t)s * M_ROWS * NCOLS];
            sc[band][t] = a;
        }
    }
    __syncthreads();

    const int steps[3] = {4, 2, 1};
    #pragma unroll
    for (int lv = 0; lv < 3; ++lv) {
        const int step = steps[lv];
        const int band = lv + 1;
        const int Mlen = PRED / step;
        float nv = 0.f;
        if (t < PRED) {
            const int s = t % step;
            const int m = t / step;
            float x1 = 0.f, x2 = 0.f;
            #pragma unroll
            for (int k = 0; k < 8; ++k) {
                int q = m + 3 - k;
                if (q >= Mlen) q -= Mlen;
                if (q < 0)     q += Mlen;
                if ((q & 1) == 0) {
                    const int idx = q * step + s;
                    x1 += sc[0][idx] * c_RL[k] + sc[band][idx] * c_RH[k];
                }
                int q2 = m + 2 - k;
                if (q2 >= Mlen) q2 -= Mlen;
                if (q2 < 0)     q2 += Mlen;
                if ((q2 & 1) == 0) {
                    const int idx2 = (q2 + 1) * step + s;
                    x2 += sc[0][idx2] * c_RL[k] + sc[band][idx2] * c_RH[k];
                }
            }
            nv = 0.5f * (x1 + x2);
        }
        __syncthreads();
        if (t < PRED) sc[0][t] = nv;
        __syncthreads();
    }

    if (t < PRED) out[(size_t)row * PRED + t] = sc[0][t];
}

// ---------------------------------------------------------------------------
extern "C" void kernel_launch(void* const* d_in, const int* in_sizes, int n_in,
                              void* d_out, int out_size)
{
    const float* X    = (const float*)d_in[0];  // (224, 49152)
    const float* W    = (const float*)d_in[1];  // (4, 49152, 336)
    const float* bias = (const float*)d_in[2];  // (4, 336)
    float* out        = (float*)d_out;          // (224, 336)

    cudaFuncSetAttribute(gemm_mma, cudaFuncAttributeMaxDynamicSharedMemorySize,
                         SMEM_NEED);
    conv_x<<<(M_ROWS * K_DIM) / (256 * 4), 256>>>(X);
    dim3 grid(NT, SPLITS);          // 14 x 21 = 294 CTAs
    gemm_mma<<<grid, THREADS, SMEM_NEED>>>(W);
    reduce_iswt<<<M_ROWS, 352>>>(bias, out);
}

// round 15
// speedup vs baseline: 1.3586x; 1.3586x over previous
#include <cuda_runtime.h>
#include <cuda_fp16.h>
#include <cstdint>

// ---------------------------------------------------------------- constants
#define M_ROWS 224      // B*N
#define K_DIM  49152
#define PRED   336
#define NCOLS  1344

#define SPLITS    21
#define BN        96
#define NT        14    // 1344/96
#define KT        64    // k per stage
#define THREADS   448   // 14 warps: 7 (m) x 2 (n), warp tile 32x48

// smem stage layout (bytes). fp16 storage, 144B row stride (128 + 16 pad)
#define A_STRIDE 144
#define B_STRIDE 144
#define A_OFF    0
#define B_OFF    32256   // 224*144
#define STAGE    46080   // + 96*144
#define NSTAGES  3
#define SMEM_NEED (NSTAGES * STAGE)   // 138240

// scratch
__device__ float  g_part[SPLITS * M_ROWS * NCOLS];
__device__ __half g_XH[(size_t)M_ROWS * K_DIM];

// db4 reconstruction filters
__constant__ float c_RL[8] = {
     0.23037781330885523f,  0.7148465705525415f,   0.6308807679295904f,
    -0.02798376941698385f, -0.18703481171888114f,  0.030841381835986965f,
     0.032883011666982945f, -0.010597401784997278f };
__constant__ float c_RH[8] = {
     0.010597401784997278f, 0.032883011666982945f, -0.030841381835986965f,
    -0.18703481171888114f,  0.02798376941698385f,   0.6308807679295904f,
    -0.7148465705525415f,   0.23037781330885523f };

// ---------------------------------------------------------------- helpers
__device__ __forceinline__ uint32_t smem_u32(const void* p) {
    uint32_t a;
    asm("{ .reg .u64 t; cvta.to.shared.u64 t, %1; cvt.u32.u64 %0, t; }"
        : "=r"(a) : "l"(p));
    return a;
}

#define CP_ASYNC16(saddr, gptr)                                               \
    asm volatile("cp.async.cg.shared.global [%0], [%1], 16;"                  \
        :: "r"(saddr), "l"(gptr))
#define CP_COMMIT() asm volatile("cp.async.commit_group;" ::: "memory")
#define CP_WAIT1()  asm volatile("cp.async.wait_group 1;" ::: "memory")

#define LDSM_X4(r0, r1, r2, r3, addr)                                         \
    asm volatile("ldmatrix.sync.aligned.m8n8.x4.shared.b16 {%0,%1,%2,%3},[%4];" \
        : "=r"(r0), "=r"(r1), "=r"(r2), "=r"(r3) : "r"(addr))

#define MMA_F16(C, A0, A1, A2, A3, B0, B1)                                    \
  asm volatile(                                                               \
      "mma.sync.aligned.m16n8k16.row.col.f32.f16.f16.f32 "                    \
      "{%0,%1,%2,%3}, {%4,%5,%6,%7}, {%8,%9}, {%0,%1,%2,%3};\n"               \
      : "+f"(C[0]), "+f"(C[1]), "+f"(C[2]), "+f"(C[3])                        \
      : "r"(A0), "r"(A1), "r"(A2), "r"(A3), "r"(B0), "r"(B1))

// quad-local 4x4 transpose: lane li of each quad holds v[j] = M[li][j];
// afterwards v[c] = M[c][li].
__device__ __forceinline__ void quad_transpose(float v[4], int li) {
    float x = (li & 1) ? v[0] : v[1];
    float y = (li & 1) ? v[2] : v[3];
    x = __shfl_xor_sync(0xffffffffu, x, 1);
    y = __shfl_xor_sync(0xffffffffu, y, 1);
    if (li & 1) { v[0] = x; v[2] = y; } else { v[1] = x; v[3] = y; }
    x = (li & 2) ? v[0] : v[2];
    y = (li & 2) ? v[1] : v[3];
    x = __shfl_xor_sync(0xffffffffu, x, 2);
    y = __shfl_xor_sync(0xffffffffu, y, 2);
    if (li & 2) { v[0] = x; v[1] = y; } else { v[2] = x; v[3] = y; }
}

// pack 4 floats -> 2 uint32 of fp16x2 (RN)
__device__ __forceinline__ uint2 pack_h4(float a, float b, float c, float d) {
    __half2 p0 = __halves2half2(__float2half_rn(a), __float2half_rn(b));
    __half2 p1 = __halves2half2(__float2half_rn(c), __float2half_rn(d));
    uint2 r;
    r.x = *reinterpret_cast<uint32_t*>(&p0);
    r.y = *reinterpret_cast<uint32_t*>(&p1);
    return r;
}

// ---------------------------------------------------------------------------
// Pre-pass: X fp32 -> fp16 (RN) once.
// ---------------------------------------------------------------------------
__global__ void __launch_bounds__(256) conv_x(const float* __restrict__ X)
{
    const size_t i = ((size_t)blockIdx.x * 256 + threadIdx.x) * 4;
    const float4 v = *reinterpret_cast<const float4*>(X + i);
    *reinterpret_cast<uint2*>(g_XH + i) = pack_h4(v.x, v.y, v.z, v.w);
}

// ---------------------------------------------------------------------------
// GEMM: C[224,1344] = X @ Wcat (split-K partials), single-product fp16 MMA.
// 3-stage pipeline, wait_group 1 (never blocks on the just-issued group),
// B prefetched 2 iterations ahead -> per-iter latency exposure removed.
// ---------------------------------------------------------------------------
__global__ void __launch_bounds__(THREADS, 1)
gemm_mma(const float* __restrict__ W)
{
    extern __shared__ char smem[];
    const uint32_t sb = smem_u32(smem);
    const int t    = threadIdx.x;
    const int lane = t & 31;
    const int warp = t >> 5;
    const int n0   = blockIdx.x * BN;
    const int split = blockIdx.y;
    // 768 k64-tiles over 21 splits: first 12 get 37, rest 36
    const int start = split * 36 + (split < 12 ? split : 12);
    const int count = 36 + (split < 12 ? 1 : 0);

    // ---- A producer: 1792 16B chunks (224 rows x 8 kc), 4/thread ----
    const char* agp[4];
    uint32_t asoff[4];
    #pragma unroll
    for (int i = 0; i < 4; ++i) {
        int c = t + i * THREADS;          // 0..1791
        int row = c >> 3;
        int kc  = c & 7;                  // 16B chunk (8 fp16) within 64-k row
        agp[i] = reinterpret_cast<const char*>(
                     g_XH + (size_t)row * K_DIM + start * KT + kc * 8);
        asoff[i] = A_OFF + row * A_STRIDE + kc * 16;
    }

    // ---- B producer: 1536 float4 chunks; quad-transpose layout.
    const int bli = t & 3;
    uint32_t bgoff[4], bsoff[4];
    #pragma unroll
    for (int i = 0; i < 4; ++i) {
        int c = t + i * THREADS;
        int cc = (c < 1536) ? c : 0;      // i=3 valid only for t<192 (warp-aligned)
        int q  = cc >> 2;
        int nc = q % 24;
        int kq = q / 24;
        int krow = kq * 4 + bli;
        int nB = n0 + nc * 4;
        int band = nB / PRED, p = nB - band * PRED;
        bgoff[i] = (uint32_t)((band * K_DIM + start * KT + krow) * PRED + p) * 4u;
        bsoff[i] = B_OFF + (nc * 4 + bli) * B_STRIDE + kq * 8;
    }
    const char* wbase = reinterpret_cast<const char*>(W);
    const bool bv3 = (t < 192);

    // ---- consumer: warp tile 32(m) x 48(n); warps 7m x 2n ----
    const int mw = warp >> 1, nw = warp & 1;
    const int mbase = mw * 32, nbase = nw * 48;
    const int li = lane & 7, lj = lane >> 3;
    int arel[2], brel[3];
    #pragma unroll
    for (int mf = 0; mf < 2; ++mf)
        arel[mf] = A_OFF + (mbase + mf * 16 + (lj & 1) * 8 + li) * A_STRIDE
                 + ((lj & 2) ? 16 : 0);
    #pragma unroll
    for (int nf = 0; nf < 3; ++nf)
        brel[nf] = B_OFF + (nbase + nf * 16 + (lj & 1) * 8 + li) * B_STRIDE
                 + ((lj & 2) ? 16 : 0);

    float acc[2][6][4];
    #pragma unroll
    for (int m = 0; m < 2; ++m)
        #pragma unroll
        for (int n = 0; n < 6; ++n)
            #pragma unroll
            for (int q = 0; q < 4; ++q) acc[m][n][q] = 0.f;

    // ---- prologue: stages 0 and 1 complete (A cp.async, B LDG+STS);
    //      fb registers hold B(2) ----
    #pragma unroll
    for (int s = 0; s < 2; ++s) {
        #pragma unroll
        for (int i = 0; i < 4; ++i)
            CP_ASYNC16(sb + s * STAGE + asoff[i], agp[i] + s * KT * 2);
        CP_COMMIT();
        #pragma unroll
        for (int i = 0; i < 4; ++i) {
            if (i == 3 && !bv3) continue;
            const uint32_t bo = (uint32_t)s * KT * PRED * 4u;
            float4 f = *reinterpret_cast<const float4*>(wbase + bgoff[i] + bo);
            float v[4] = { f.x, f.y, f.z, f.w };
            quad_transpose(v, bli);
            *reinterpret_cast<uint2*>(smem + s * STAGE + bsoff[i]) =
                pack_h4(v[0], v[1], v[2], v[3]);
        }
    }
    float4 fb[4];
    {
        const uint32_t bo = 2u * KT * PRED * 4u;   // count >= 36 > 2 always
        #pragma unroll
        for (int i = 0; i < 4; ++i)
            fb[i] = (i < 3 || bv3)
                  ? *reinterpret_cast<const float4*>(wbase + bgoff[i] + bo)
                  : make_float4(0, 0, 0, 0);
    }
    CP_WAIT1();              // A(0) complete (A(1) may be in flight)
    __syncthreads();

    // ---- main loop: iter it computes stage it%3.
    // Invariant at loop top: stages it, it+1 complete in smem;
    // fb = B(it+2); A(it+1) group possibly outstanding. ----
    int ss = 0;
    for (int it = 0; it < count; ++it) {
        const int wr = (ss + 2 >= NSTAGES) ? ss - 1 : ss + 2;   // (it+2)%3
        const uint32_t ab = sb + ss * STAGE;
        const bool v2 = (it + 2 < count);
        const bool v3 = (it + 3 < count);

        // issue A(it+2); always commit (keeps wait_group accounting exact)
        if (v2) {
            const uint32_t nsb = sb + wr * STAGE;
            const uint32_t ao = (uint32_t)(it + 2) * KT * 2u;
            #pragma unroll
            for (int i = 0; i < 4; ++i)
                CP_ASYNC16(nsb + asoff[i], agp[i] + ao);
        }
        CP_COMMIT();

        // start LDG of B(it+3) — a full iteration of latency slack
        float4 fbn[4];
        if (v3) {
            const uint32_t bo = (uint32_t)(it + 3) * KT * PRED * 4u;
            #pragma unroll
            for (int i = 0; i < 4; ++i)
                fbn[i] = (i < 3 || bv3)
                       ? *reinterpret_cast<const float4*>(wbase + bgoff[i] + bo)
                       : make_float4(0, 0, 0, 0);
        }

        // compute on stage ss: 4 x k16
        #pragma unroll
        for (int k16 = 0; k16 < 4; ++k16) {
            uint32_t a[2][4];
            #pragma unroll
            for (int mf = 0; mf < 2; ++mf)
                LDSM_X4(a[mf][0], a[mf][1], a[mf][2], a[mf][3],
                        ab + arel[mf] + k16 * 32);
            #pragma unroll
            for (int nf = 0; nf < 3; ++nf) {
                uint32_t r0, r1, r2, r3;
                LDSM_X4(r0, r1, r2, r3, ab + brel[nf] + k16 * 32);
                #pragma unroll
                for (int mf = 0; mf < 2; ++mf) {
                    MMA_F16(acc[mf][2*nf],   a[mf][0], a[mf][1], a[mf][2], a[mf][3], r0, r2);
                    MMA_F16(acc[mf][2*nf+1], a[mf][0], a[mf][1], a[mf][2], a[mf][3], r1, r3);
                }
            }
        }

        // store B(it+2) (loaded 2 iterations ago) into stage wr
        if (v2) {
            char* nst = smem + wr * STAGE;
            #pragma unroll
            for (int i = 0; i < 4; ++i) {
                if (i == 3 && !bv3) continue;
                float v[4] = { fb[i].x, fb[i].y, fb[i].z, fb[i].w };
                quad_transpose(v, bli);
                *reinterpret_cast<uint2*>(nst + bsoff[i]) =
                    pack_h4(v[0], v[1], v[2], v[3]);
            }
        }

        CP_WAIT1();          // A(it+1) complete; A(it+2) may remain in flight
        __syncthreads();

        #pragma unroll
        for (int i = 0; i < 4; ++i) fb[i] = fbn[i];
        ss = (ss + 1 == NSTAGES) ? 0 : ss + 1;
    }

    // ---- epilogue: split-K partials ----
    float* gp = g_part + (size_t)split * M_ROWS * NCOLS;
    const int rr = lane >> 2, cc = (lane & 3) * 2;
    #pragma unroll
    for (int mf = 0; mf < 2; ++mf) {
        const int row = mbase + mf * 16 + rr;
        #pragma unroll
        for (int ns = 0; ns < 6; ++ns) {
            const int col = n0 + nbase + ns * 8 + cc;
            *reinterpret_cast<float2*>(gp + (size_t)row * NCOLS + col) =
                make_float2(acc[mf][ns][0], acc[mf][ns][1]);
            *reinterpret_cast<float2*>(gp + (size_t)(row + 8) * NCOLS + col) =
                make_float2(acc[mf][ns][2], acc[mf][ns][3]);
        }
    }
}

// ---------------------------------------------------------------------------
// Split-K reduce + bias + 3-level inverse SWT (db4, periodization)
// ---------------------------------------------------------------------------
__global__ void reduce_iswt(const float* __restrict__ bias, float* __restrict__ out)
{
    __shared__ float sc[4][PRED];
    const int t   = threadIdx.x;
    const int row = blockIdx.x;

    if (t < PRED) {
        #pragma unroll
        for (int band = 0; band < 4; ++band) {
            float a = bias[band * PRED + t];
            const float* gp = g_part + (size_t)row * NCOLS + band * PRED + t;
            #pragma unroll
            for (int s = 0; s < SPLITS; ++s)
                a += gp[(size_t)s * M_ROWS * NCOLS];
            sc[band][t] = a;
        }
    }
    __syncthreads();

    const int steps[3] = {4, 2, 1};
    #pragma unroll
    for (int lv = 0; lv < 3; ++lv) {
        const int step = steps[lv];
        const int band = lv + 1;
        const int Mlen = PRED / step;
        float nv = 0.f;
        if (t < PRED) {
            const int s = t % step;
            const int m = t / step;
            float x1 = 0.f, x2 = 0.f;
            #pragma unroll
            for (int k = 0; k < 8; ++k) {
                int q = m + 3 - k;
                if (q >= Mlen) q -= Mlen;
                if (q < 0)     q += Mlen;
                if ((q & 1) == 0) {
                    const int idx = q * step + s;
                    x1 += sc[0][idx] * c_RL[k] + sc[band][idx] * c_RH[k];
                }
                int q2 = m + 2 - k;
                if (q2 >= Mlen) q2 -= Mlen;
                if (q2 < 0)     q2 += Mlen;
                if ((q2 & 1) == 0) {
                    const int idx2 = (q2 + 1) * step + s;
                    x2 += sc[0][idx2] * c_RL[k] + sc[band][idx2] * c_RH[k];
                }
            }
            nv = 0.5f * (x1 + x2);
        }
        __syncthreads();
        if (t < PRED) sc[0][t] = nv;
        __syncthreads();
    }

    if (t < PRED) out[(size_t)row * PRED + t] = sc[0][t];
}

// ---------------------------------------------------------------------------
extern "C" void kernel_launch(void* const* d_in, const int* in_sizes, int n_in,
                              void* d_out, int out_size)
{
    const float* X    = (const float*)d_in[0];  // (224, 49152)
    const float* W    = (const float*)d_in[1];  // (4, 49152, 336)
    const float* bias = (const float*)d_in[2];  // (4, 336)
    float* out        = (float*)d_out;          // (224, 336)

    cudaFuncSetAttribute(gemm_mma, cudaFuncAttributeMaxDynamicSharedMemorySize,
                         SMEM_NEED);
    conv_x<<<(M_ROWS * K_DIM) / (256 * 4), 256>>>(X);
    dim3 grid(NT, SPLITS);          // 14 x 21 = 294 CTAs
    gemm_mma<<<grid, THREADS, SMEM_NEED>>>(W);
    reduce_iswt<<<M_ROWS, 352>>>(bias, out);
}

// round 17
// speedup vs baseline: 1.4587x; 1.0737x over previous
#include <cuda_runtime.h>
#include <cuda_fp16.h>
#include <cstdint>

// ---------------------------------------------------------------- constants
#define M_ROWS 224      // B*N
#define K_DIM  49152
#define PRED   336
#define NCOLS  1344

#define SPLITS    21
#define BN        96
#define NT        14    // 1344/96
#define KT        64    // k per stage
#define THREADS   672   // 21 warps: 7 (m) x 3 (n), warp tile 32x32

// smem stage layout (bytes). fp16 storage, 144B row stride (128 + 16 pad)
#define A_STRIDE 144
#define B_STRIDE 144
#define A_OFF    0
#define B_OFF    32256   // 224*144
#define STAGE    46080   // + 96*144
#define NSTAGES  3
#define SMEM_NEED (NSTAGES * STAGE)   // 138240

// scratch
__device__ float  g_part[SPLITS * M_ROWS * NCOLS];
__device__ __half g_XH[(size_t)M_ROWS * K_DIM];

// db4 reconstruction filters
__constant__ float c_RL[8] = {
     0.23037781330885523f,  0.7148465705525415f,   0.6308807679295904f,
    -0.02798376941698385f, -0.18703481171888114f,  0.030841381835986965f,
     0.032883011666982945f, -0.010597401784997278f };
__constant__ float c_RH[8] = {
     0.010597401784997278f, 0.032883011666982945f, -0.030841381835986965f,
    -0.18703481171888114f,  0.02798376941698385f,   0.6308807679295904f,
    -0.7148465705525415f,   0.23037781330885523f };

// ---------------------------------------------------------------- helpers
__device__ __forceinline__ uint32_t smem_u32(const void* p) {
    uint32_t a;
    asm("{ .reg .u64 t; cvta.to.shared.u64 t, %1; cvt.u32.u64 %0, t; }"
        : "=r"(a) : "l"(p));
    return a;
}

#define CP_ASYNC16(saddr, gptr)                                               \
    asm volatile("cp.async.cg.shared.global [%0], [%1], 16;"                  \
        :: "r"(saddr), "l"(gptr))
#define CP_COMMIT() asm volatile("cp.async.commit_group;" ::: "memory")
#define CP_WAIT1()  asm volatile("cp.async.wait_group 1;" ::: "memory")

#define LDSM_X4(r0, r1, r2, r3, addr)                                         \
    asm volatile("ldmatrix.sync.aligned.m8n8.x4.shared.b16 {%0,%1,%2,%3},[%4];" \
        : "=r"(r0), "=r"(r1), "=r"(r2), "=r"(r3) : "r"(addr))

#define MMA_F16(C, A0, A1, A2, A3, B0, B1)                                    \
  asm volatile(                                                               \
      "mma.sync.aligned.m16n8k16.row.col.f32.f16.f16.f32 "                    \
      "{%0,%1,%2,%3}, {%4,%5,%6,%7}, {%8,%9}, {%0,%1,%2,%3};\n"               \
      : "+f"(C[0]), "+f"(C[1]), "+f"(C[2]), "+f"(C[3])                        \
      : "r"(A0), "r"(A1), "r"(A2), "r"(A3), "r"(B0), "r"(B1))

// quad-local 4x4 transpose: lane li of each quad holds v[j] = M[li][j];
// afterwards v[c] = M[c][li].
__device__ __forceinline__ void quad_transpose(float v[4], int li) {
    float x = (li & 1) ? v[0] : v[1];
    float y = (li & 1) ? v[2] : v[3];
    x = __shfl_xor_sync(0xffffffffu, x, 1);
    y = __shfl_xor_sync(0xffffffffu, y, 1);
    if (li & 1) { v[0] = x; v[2] = y; } else { v[1] = x; v[3] = y; }
    x = (li & 2) ? v[0] : v[2];
    y = (li & 2) ? v[1] : v[3];
    x = __shfl_xor_sync(0xffffffffu, x, 2);
    y = __shfl_xor_sync(0xffffffffu, y, 2);
    if (li & 2) { v[0] = x; v[1] = y; } else { v[2] = x; v[3] = y; }
}

// pack 4 floats -> 2 uint32 of fp16x2 (RN)
__device__ __forceinline__ uint2 pack_h4(float a, float b, float c, float d) {
    __half2 p0 = __halves2half2(__float2half_rn(a), __float2half_rn(b));
    __half2 p1 = __halves2half2(__float2half_rn(c), __float2half_rn(d));
    uint2 r;
    r.x = *reinterpret_cast<uint32_t*>(&p0);
    r.y = *reinterpret_cast<uint32_t*>(&p1);
    return r;
}

// ---------------------------------------------------------------------------
// Pre-pass: X fp32 -> fp16 (RN) once.
// ---------------------------------------------------------------------------
__global__ void __launch_bounds__(256) conv_x(const float* __restrict__ X)
{
    const size_t i = ((size_t)blockIdx.x * 256 + threadIdx.x) * 4;
    const float4 v = *reinterpret_cast<const float4*>(X + i);
    *reinterpret_cast<uint2*>(g_XH + i) = pack_h4(v.x, v.y, v.z, v.w);
}

// ---------------------------------------------------------------------------
// GEMM: C[224,1344] = X @ Wcat (split-K partials), single-product fp16 MMA.
// 21 warps (7m x 3n, warp tile 32x32): 5.25 warps/SMSP to absorb the
// dependency latency that bound the 14-warp version. 3-stage pipeline,
// wait_group 1; B STS moved to loop top (single fb buffer, fits 96 regs).
// ---------------------------------------------------------------------------
__global__ void __launch_bounds__(THREADS, 1)
gemm_mma(const float* __restrict__ W)
{
    extern __shared__ char smem[];
    const uint32_t sb = smem_u32(smem);
    const int t    = threadIdx.x;
    const int lane = t & 31;
    const int warp = t >> 5;
    const int n0   = blockIdx.x * BN;
    const int split = blockIdx.y;
    // 768 k64-tiles over 21 splits: first 12 get 37, rest 36
    const int start = split * 36 + (split < 12 ? split : 12);
    const int count = 36 + (split < 12 ? 1 : 0);

    // ---- A producer: 1792 16B chunks (224 rows x 8 kc), <=3/thread ----
    const char* agp[3];
    uint32_t asoff[3];
    #pragma unroll
    for (int i = 0; i < 3; ++i) {
        int c = t + i * THREADS;          // 0..2015; valid < 1792
        int cc = (c < 1792) ? c : 0;
        int row = cc >> 3;
        int kc  = cc & 7;                 // 16B chunk (8 fp16) within 64-k row
        agp[i] = reinterpret_cast<const char*>(
                     g_XH + (size_t)row * K_DIM + start * KT + kc * 8);
        asoff[i] = A_OFF + row * A_STRIDE + kc * 16;
    }
    const bool av2 = (t < 448);           // chunk i=2 valid (warp-aligned)

    // ---- B producer: 1536 float4 chunks; quad-transpose layout. ----
    // chunk c: q=c>>2, nc=q%24 (4-col group), kq=q/24 (k-quad 0..15), li=c&3.
    const int bli = t & 3;
    uint32_t bgoff[3], bsoff[3];
    #pragma unroll
    for (int i = 0; i < 3; ++i) {
        int c = t + i * THREADS;
        int cc = (c < 1536) ? c : 0;      // i=2 valid only for t<192 (warp-aligned)
        int q  = cc >> 2;
        int nc = q % 24;
        int kq = q / 24;
        int krow = kq * 4 + bli;
        int nB = n0 + nc * 4;
        int band = nB / PRED, p = nB - band * PRED;
        bgoff[i] = (uint32_t)((band * K_DIM + start * KT + krow) * PRED + p) * 4u;
        bsoff[i] = B_OFF + (nc * 4 + bli) * B_STRIDE + kq * 8;
    }
    const char* wbase = reinterpret_cast<const char*>(W);
    const bool bv2 = (t < 192);           // chunk i=2 valid

    // ---- consumer: warp tile 32(m) x 32(n); warps 7m x 3n ----
    const int mw = warp / 3, nw = warp - mw * 3;
    const int mbase = mw * 32, nbase = nw * 32;
    const int li = lane & 7, lj = lane >> 3;
    int arel[2], brel[2];
    #pragma unroll
    for (int mf = 0; mf < 2; ++mf)
        arel[mf] = A_OFF + (mbase + mf * 16 + (lj & 1) * 8 + li) * A_STRIDE
                 + ((lj & 2) ? 16 : 0);
    #pragma unroll
    for (int nf = 0; nf < 2; ++nf)
        brel[nf] = B_OFF + (nbase + nf * 16 + (lj & 1) * 8 + li) * B_STRIDE
                 + ((lj & 2) ? 16 : 0);

    float acc[2][4][4];
    #pragma unroll
    for (int m = 0; m < 2; ++m)
        #pragma unroll
        for (int n = 0; n < 4; ++n)
            #pragma unroll
            for (int q = 0; q < 4; ++q) acc[m][n][q] = 0.f;

    // ---- prologue: stages 0 and 1 complete; fb holds B(2) ----
    #pragma unroll
    for (int s = 0; s < 2; ++s) {
        #pragma unroll
        for (int i = 0; i < 3; ++i) {
            if (i == 2 && !av2) continue;
            CP_ASYNC16(sb + s * STAGE + asoff[i], agp[i] + s * KT * 2);
        }
        CP_COMMIT();
        #pragma unroll
        for (int i = 0; i < 3; ++i) {
            if (i == 2 && !bv2) continue;
            const uint32_t bo = (uint32_t)s * KT * PRED * 4u;
            float4 f = *reinterpret_cast<const float4*>(wbase + bgoff[i] + bo);
            float v[4] = { f.x, f.y, f.z, f.w };
            quad_transpose(v, bli);
            *reinterpret_cast<uint2*>(smem + s * STAGE + bsoff[i]) =
                pack_h4(v[0], v[1], v[2], v[3]);
        }
    }
    float4 fb[3];
    {
        const uint32_t bo = 2u * KT * PRED * 4u;   // count >= 36 > 2 always
        #pragma unroll
        for (int i = 0; i < 3; ++i)
            fb[i] = (i < 2 || bv2)
                  ? *reinterpret_cast<const float4*>(wbase + bgoff[i] + bo)
                  : make_float4(0, 0, 0, 0);
    }
    CP_WAIT1();              // A(0) complete (A(1) may be in flight)
    __syncthreads();

    // ---- main loop: iter it computes stage it%3.
    // Invariant at loop top: stages it, it+1 complete in smem (A and B);
    // fb = B(it+2); A(it+1) group possibly outstanding;
    // stage (it+2)%3 is free (consumed at it-1). ----
    int ss = 0;
    for (int it = 0; it < count; ++it) {
        const int wr = (ss + 2 >= NSTAGES) ? ss - 1 : ss + 2;   // (it+2)%3
        const uint32_t ab = sb + ss * STAGE;
        const bool v2 = (it + 2 < count);
        const bool v3 = (it + 3 < count);

        // store B(it+2) (in fb) into stage wr, then refill fb with B(it+3)
        if (v2) {
            char* nst = smem + wr * STAGE;
            #pragma unroll
            for (int i = 0; i < 3; ++i) {
                if (i == 2 && !bv2) continue;
                float v[4] = { fb[i].x, fb[i].y, fb[i].z, fb[i].w };
                quad_transpose(v, bli);
                *reinterpret_cast<uint2*>(nst + bsoff[i]) =
                    pack_h4(v[0], v[1], v[2], v[3]);
            }
        }
        if (v3) {
            const uint32_t bo = (uint32_t)(it + 3) * KT * PRED * 4u;
            #pragma unroll
            for (int i = 0; i < 3; ++i)
                fb[i] = (i < 2 || bv2)
                      ? *reinterpret_cast<const float4*>(wbase + bgoff[i] + bo)
                      : make_float4(0, 0, 0, 0);
        }

        // issue A(it+2); always commit (keeps wait_group accounting exact)
        if (v2) {
            const uint32_t nsb = sb + wr * STAGE;
            const uint32_t ao = (uint32_t)(it + 2) * KT * 2u;
            #pragma unroll
            for (int i = 0; i < 3; ++i) {
                if (i == 2 && !av2) continue;
                CP_ASYNC16(nsb + asoff[i], agp[i] + ao);
            }
        }
        CP_COMMIT();

        // compute on stage ss: 4 x k16
        #pragma unroll
        for (int k16 = 0; k16 < 4; ++k16) {
            uint32_t a[2][4];
            #pragma unroll
            for (int mf = 0; mf < 2; ++mf)
                LDSM_X4(a[mf][0], a[mf][1], a[mf][2], a[mf][3],
                        ab + arel[mf] + k16 * 32);
            #pragma unroll
            for (int nf = 0; nf < 2; ++nf) {
                // non-trans LDSM on [n][k]: r0=(n0-7,k0-7) r1=(n8-15,k0-7)
                //                           r2=(n0-7,k8-15) r3=(n8-15,k8-15)
                uint32_t r0, r1, r2, r3;
                LDSM_X4(r0, r1, r2, r3, ab + brel[nf] + k16 * 32);
                #pragma unroll
                for (int mf = 0; mf < 2; ++mf) {
                    MMA_F16(acc[mf][2*nf],   a[mf][0], a[mf][1], a[mf][2], a[mf][3], r0, r2);
                    MMA_F16(acc[mf][2*nf+1], a[mf][0], a[mf][1], a[mf][2], a[mf][3], r1, r3);
                }
            }
        }

        CP_WAIT1();          // A(it+1) complete; A(it+2) may remain in flight
        __syncthreads();
        ss = (ss + 1 == NSTAGES) ? 0 : ss + 1;
    }

    // ---- epilogue: split-K partials ----
    float* gp = g_part + (size_t)split * M_ROWS * NCOLS;
    const int rr = lane >> 2, cc = (lane & 3) * 2;
    #pragma unroll
    for (int mf = 0; mf < 2; ++mf) {
        const int row = mbase + mf * 16 + rr;
        #pragma unroll
        for (int ns = 0; ns < 4; ++ns) {
            const int col = n0 + nbase + ns * 8 + cc;
            *reinterpret_cast<float2*>(gp + (size_t)row * NCOLS + col) =
                make_float2(acc[mf][ns][0], acc[mf][ns][1]);
            *reinterpret_cast<float2*>(gp + (size_t)(row + 8) * NCOLS + col) =
                make_float2(acc[mf][ns][2], acc[mf][ns][3]);
        }
    }
}

// ---------------------------------------------------------------------------
// Split-K reduce + bias + 3-level inverse SWT (db4, periodization)
// ---------------------------------------------------------------------------
__global__ void reduce_iswt(const float* __restrict__ bias, float* __restrict__ out)
{
    __shared__ float sc[4][PRED];
    const int t   = threadIdx.x;
    const int row = blockIdx.x;

    if (t < PRED) {
        #pragma unroll
        for (int band = 0; band < 4; ++band) {
            float a = bias[band * PRED + t];
            const float* gp = g_part + (size_t)row * NCOLS + band * PRED + t;
            #pragma unroll
            for (int s = 0; s < SPLITS; ++s)
                a += gp[(size_t)s * M_ROWS * NCOLS];
            sc[band][t] = a;
        }
    }
    __syncthreads();

    const int steps[3] = {4, 2, 1};
    #pragma unroll
    for (int lv = 0; lv < 3; ++lv) {
        const int step = steps[lv];
        const int band = lv + 1;
        const int Mlen = PRED / step;
        float nv = 0.f;
        if (t < PRED) {
            const int s = t % step;
            const int m = t / step;
            float x1 = 0.f, x2 = 0.f;
            #pragma unroll
            for (int k = 0; k < 8; ++k) {
                int q = m + 3 - k;
                if (q >= Mlen) q -= Mlen;
                if (q < 0)     q += Mlen;
                if ((q & 1) == 0) {
                    const int idx = q * step + s;
                    x1 += sc[0][idx] * c_RL[k] + sc[band][idx] * c_RH[k];
                }
                int q2 = m + 2 - k;
                if (q2 >= Mlen) q2 -= Mlen;
                if (q2 < 0)     q2 += Mlen;
                if ((q2 & 1) == 0) {
                    const int idx2 = (q2 + 1) * step + s;
                    x2 += sc[0][idx2] * c_RL[k] + sc[band][idx2] * c_RH[k];
                }
            }
            nv = 0.5f * (x1 + x2);
        }
        __syncthreads();
        if (t < PRED) sc[0][t] = nv;
        __syncthreads();
    }

    if (t < PRED) out[(size_t)row * PRED + t] = sc[0][t];
}

// ---------------------------------------------------------------------------
extern "C" void kernel_launch(void* const* d_in, const int* in_sizes, int n_in,
                              void* d_out, int out_size)
{
    const float* X    = (const float*)d_in[0];  // (224, 49152)
    const float* W    = (const float*)d_in[1];  // (4, 49152, 336)
    const float* bias = (const float*)d_in[2];  // (4, 336)
    float* out        = (float*)d_out;          // (224, 336)

    cudaFuncSetAttribute(gemm_mma, cudaFuncAttributeMaxDynamicSharedMemorySize,
                         SMEM_NEED);
    conv_x<<<(M_ROWS * K_DIM) / (256 * 4), 256>>>(X);
    dim3 grid(NT, SPLITS);          // 14 x 21 = 294 CTAs
    gemm_mma<<<grid, THREADS, SMEM_NEED>>>(W);
    reduce_iswt<<<M_ROWS, 352>>>(bias, out);
}